// round 7
// baseline (speedup 1.0000x reference)
#include <cuda_runtime.h>

#define NB 8
#define NL 4096
#define NK 16
#define ND 128

#define QPB 64           // queries per block
#define TPB 128          // threads per block (2 threads per query)
#define TILE 1024        // candidates staged per smem tile
#define NTILES (NL / TILE)
#define BCAP 40          // per-thread candidate buffer capacity

// scratch: neighbor indices (allocation-free rule -> __device__ global)
__device__ int g_nbr[NB * NL * NK];

// ---------------------------------------------------------------------------
// sorted-ascending top-16 insert, split at the median. Strict '<' everywhere
// => stable (lower index wins ties within a thread's increasing-index scan).
// ---------------------------------------------------------------------------
__device__ __forceinline__ void ins16(float (&bd)[NK], int (&bi)[NK],
                                      float d, int j)
{
    if (d < bd[7]) {
#pragma unroll
        for (int i = 15; i > 8; --i) { bd[i] = bd[i - 1]; bi[i] = bi[i - 1]; }
        bd[8] = bd[7]; bi[8] = bi[7];
        float cd = d; int ci = j;
#pragma unroll
        for (int i = 0; i < 8; ++i) {
            if (cd < bd[i]) {
                float td = bd[i]; bd[i] = cd; cd = td;
                int   ti = bi[i]; bi[i] = ci; ci = ti;
            }
        }
    } else {
        float cd = d; int ci = j;
#pragma unroll
        for (int i = 8; i < 16; ++i) {
            if (cd < bd[i]) {
                float td = bd[i]; bd[i] = cd; cd = td;
                int   ti = bi[i]; bi[i] = ci; ci = ti;
            }
        }
    }
}

__device__ __forceinline__ unsigned long long pack2(float lo, float hi)
{
    unsigned long long r;
    asm("mov.b64 %0, {%1, %2};" : "=l"(r) : "f"(lo), "f"(hi));
    return r;
}

// packed squared-distance for one PAIR of candidates (exact unfused IEEE rn)
__device__ __forceinline__ void dist2(unsigned long long x2, unsigned long long y2,
                                      unsigned long long z2,
                                      unsigned long long ncx2, unsigned long long ncy2,
                                      unsigned long long ncz2,
                                      float& d0, float& d1)
{
    unsigned long long dx2, dy2, dz2, m0, m1, m2, s0, dd;
    asm("add.rn.f32x2 %0, %1, %2;" : "=l"(dx2) : "l"(x2), "l"(ncx2));
    asm("add.rn.f32x2 %0, %1, %2;" : "=l"(dy2) : "l"(y2), "l"(ncy2));
    asm("add.rn.f32x2 %0, %1, %2;" : "=l"(dz2) : "l"(z2), "l"(ncz2));
    asm("mul.rn.f32x2 %0, %1, %2;" : "=l"(m0) : "l"(dx2), "l"(dx2));
    asm("mul.rn.f32x2 %0, %1, %2;" : "=l"(m1) : "l"(dy2), "l"(dy2));
    asm("mul.rn.f32x2 %0, %1, %2;" : "=l"(m2) : "l"(dz2), "l"(dz2));
    asm("add.rn.f32x2 %0, %1, %2;" : "=l"(s0) : "l"(m0), "l"(m1));
    asm("add.rn.f32x2 %0, %1, %2;" : "=l"(dd) : "l"(s0), "l"(m2));
    asm("mov.b64 {%0, %1}, %2;" : "=f"(d0), "=f"(d1) : "l"(dd));
}

// ---------------------------------------------------------------------------
// Kernel 1: brute-force 16-NN, 2 threads per query, 16 candidates per
// iteration (12x LDS.128, 8 independent packed f32x2 chains), buffered
// pushes compacted with popc-prefix (short dependency chain), warp-
// synchronized flushes, exact 2-way merge.
// ---------------------------------------------------------------------------
__global__ __launch_bounds__(TPB, 4)
void knn_kernel(const float* __restrict__ frame,
                float* __restrict__ eucl_out)
{
    __shared__ __align__(16) unsigned char smem_raw[16384];
    float* sx = (float*)smem_raw;            // TILE floats
    float* sy = sx + TILE;
    float* sz = sy + TILE;

    const int tid = threadIdx.x;
    const int h   = tid & 1;                 // which half of candidate space
    const int q   = blockIdx.x * QPB + (tid >> 1);   // global query id
    const int b   = q / NL;
    const int ql  = q - b * NL;
    const float* fb = frame + (size_t)b * NL * 12;   // [L][4][3]
    const float* fq = fb + ql * 12;

    const float cx = fq[0], cy = fq[1], cz = fq[2];
    const unsigned long long ncx2 = pack2(-cx, -cx);
    const unsigned long long ncy2 = pack2(-cy, -cy);
    const unsigned long long ncz2 = pack2(-cz, -cz);

    float bd[NK];
    int   bi[NK];
#pragma unroll
    for (int i = 0; i < NK; i++) { bd[i] = 3.0e38f; bi[i] = 0; }

    float2 lbuf[BCAP];                       // local-mem candidate buffer
    int    cnt = 0;
    float  tau = 3.0e38f;                    // stale copy of bd[15] (only shrinks)

    const float4* x4 = (const float4*)sx;
    const float4* y4 = (const float4*)sy;
    const float4* z4 = (const float4*)sz;

    for (int t = 0; t < NTILES; ++t) {
        const int tb = t * TILE;
        __syncthreads();
        {   // stage tile centers (rows are 48B = 3 x float4)
            const float4* src = (const float4*)(fb + (size_t)tb * 12);
            for (int i = tid; i < TILE; i += TPB) {
                float4 r = src[i * 3];       // (x, y, z, junk)
                sx[i] = r.x; sy[i] = r.y; sz[i] = r.z;
            }
        }
        __syncthreads();

        // thread owns 16 consecutive candidates: 32*m + 16*h .. +15
        for (int m = 0; m < TILE / 32; ++m) {
            const int g0 = 8 * m + 4 * h;    // float4 group index
            float4 xa = x4[g0], xb = x4[g0 + 1], xc = x4[g0 + 2], xd = x4[g0 + 3];
            float4 ya = y4[g0], yb = y4[g0 + 1], yc = y4[g0 + 2], yd = y4[g0 + 3];
            float4 za = z4[g0], zb = z4[g0 + 1], zc = z4[g0 + 2], zd = z4[g0 + 3];

            float d[16];
            dist2(pack2(xa.x, xa.y), pack2(ya.x, ya.y), pack2(za.x, za.y),
                  ncx2, ncy2, ncz2, d[0], d[1]);
            dist2(pack2(xa.z, xa.w), pack2(ya.z, ya.w), pack2(za.z, za.w),
                  ncx2, ncy2, ncz2, d[2], d[3]);
            dist2(pack2(xb.x, xb.y), pack2(yb.x, yb.y), pack2(zb.x, zb.y),
                  ncx2, ncy2, ncz2, d[4], d[5]);
            dist2(pack2(xb.z, xb.w), pack2(yb.z, yb.w), pack2(zb.z, zb.w),
                  ncx2, ncy2, ncz2, d[6], d[7]);
            dist2(pack2(xc.x, xc.y), pack2(yc.x, yc.y), pack2(zc.x, zc.y),
                  ncx2, ncy2, ncz2, d[8], d[9]);
            dist2(pack2(xc.z, xc.w), pack2(yc.z, yc.w), pack2(zc.z, zc.w),
                  ncx2, ncy2, ncz2, d[10], d[11]);
            dist2(pack2(xd.x, xd.y), pack2(yd.x, yd.y), pack2(zd.x, zd.y),
                  ncx2, ncy2, ncz2, d[12], d[13]);
            dist2(pack2(xd.z, xd.w), pack2(yd.z, yd.w), pack2(zd.z, zd.w),
                  ncx2, ncy2, ncz2, d[14], d[15]);

            const int j0 = tb + 32 * m + 16 * h;

            // group pass-masks (parallel FSETPs, shallow combine)
            unsigned mA = 0, mB = 0, mC = 0, mD = 0;
#pragma unroll
            for (int i = 0; i < 4; ++i) {
                mA |= (d[i]      < tau) ? (1u << i) : 0u;
                mB |= (d[4 + i]  < tau) ? (1u << i) : 0u;
                mC |= (d[8 + i]  < tau) ? (1u << i) : 0u;
                mD |= (d[12 + i] < tau) ? (1u << i) : 0u;
            }
            // group bases via popc prefix (chain depth ~3 IADD)
            const int baseA = cnt;
            const int baseB = baseA + __popc(mA);
            const int baseC = baseB + __popc(mB);
            const int baseD = baseC + __popc(mC);
            cnt = baseD + __popc(mD);

            // serial only within each group of 4 (independent across groups)
            {
                int p = baseA;
#pragma unroll
                for (int i = 0; i < 4; ++i)
                    if (d[i] < tau) { lbuf[p] = make_float2(d[i], __int_as_float(j0 + i)); p++; }
            }
            {
                int p = baseB;
#pragma unroll
                for (int i = 0; i < 4; ++i)
                    if (d[4 + i] < tau) { lbuf[p] = make_float2(d[4 + i], __int_as_float(j0 + 4 + i)); p++; }
            }
            {
                int p = baseC;
#pragma unroll
                for (int i = 0; i < 4; ++i)
                    if (d[8 + i] < tau) { lbuf[p] = make_float2(d[8 + i], __int_as_float(j0 + 8 + i)); p++; }
            }
            {
                int p = baseD;
#pragma unroll
                for (int i = 0; i < 4; ++i)
                    if (d[12 + i] < tau) { lbuf[p] = make_float2(d[12 + i], __int_as_float(j0 + 12 + i)); p++; }
            }

            // warp-synchronized flush: all lanes' inserts coalesce here
            if (__any_sync(0xffffffffu, cnt > BCAP - 16)) {
                for (int i = 0; i < cnt; ++i) {
                    float dv = lbuf[i].x;
                    if (dv < bd[NK - 1])
                        ins16(bd, bi, dv, __float_as_int(lbuf[i].y));
                }
                cnt = 0;
                tau = bd[NK - 1];
            }
        }
    }

    // final flush
    for (int i = 0; i < cnt; ++i) {
        float dv = lbuf[i].x;
        if (dv < bd[NK - 1])
            ins16(bd, bi, dv, __float_as_int(lbuf[i].y));
    }

    // -------- merge the two half-lists per query (exact, stable) ----------
    __syncthreads();                          // done reading tile smem
    float* md = (float*)smem_raw;             // 128*16 floats = 8KB
    int*   mi = (int*)(smem_raw + TPB * NK * 4);
#pragma unroll
    for (int k = 0; k < NK; ++k) { md[tid * NK + k] = bd[k]; mi[tid * NK + k] = bi[k]; }
    __syncthreads();

    if (h == 0) {
        const int pa = tid * NK, pb = pa + NK;
        int ia = 0, ib = 0;
        int fi_[NK];
#pragma unroll
        for (int k = 0; k < NK; ++k) {
            float da = md[pa + ia], db = md[pb + ib];
            int   ja = mi[pa + ia], jb = mi[pb + ib];
            bool ta = (da < db) || (da == db && ja < jb);   // lexicographic (d, idx)
            fi_[k] = ta ? ja : jb;
            if (ta) ia++; else ib++;
        }

        // rotation rows: frame[b,q,1:4,:]  (R[c][r] = fq[3 + c*3 + r])
        float R[3][3];
#pragma unroll
        for (int c = 0; c < 3; c++)
#pragma unroll
            for (int r = 0; r < 3; r++)
                R[c][r] = fq[3 + c * 3 + r];

        const size_t base = (size_t)q * NK;
        float* eo = eucl_out + base * 3;
#pragma unroll
        for (int k = 0; k < NK; ++k) {
            const int n = fi_[k];
            g_nbr[base + k] = n;
            const float* fn = fb + (size_t)n * 12;
            float d0 = fn[0] - cx;
            float d1 = fn[1] - cy;
            float d2 = fn[2] - cz;
            eo[k * 3 + 0] = d0 * R[0][0] + d1 * R[1][0] + d2 * R[2][0];
            eo[k * 3 + 1] = d0 * R[0][1] + d1 * R[1][1] + d2 * R[2][1];
            eo[k * 3 + 2] = d0 * R[0][2] + d1 * R[1][2] + d2 * R[2][2];
        }
    }
}

// ---------------------------------------------------------------------------
// Kernel 2: attribute gather (best measured config: 4 rows/warp, 8 lanes per
// row, 4 float4 per lane -> ~44us, near write-BW floor).
// ---------------------------------------------------------------------------
__global__ __launch_bounds__(256, 8)
void gather_kernel(const float* __restrict__ attr,
                   float* __restrict__ gout)
{
    const int warp = (blockIdx.x * 256 + threadIdx.x) >> 5;
    const int lane = threadIdx.x & 31;
    const int row  = warp * 4 + (lane >> 3);      // 4 rows per warp
    const int l8   = lane & 7;

    const int b = row / (NL * NK);
    const int n = g_nbr[row];

    const float4* src = (const float4*)(attr + ((size_t)b * NL + n) * ND);
    float4*       dst = (float4*)(gout + (size_t)row * ND);

    float4 v0 = src[l8];
    float4 v1 = src[l8 + 8];
    float4 v2 = src[l8 + 16];
    float4 v3 = src[l8 + 24];
    dst[l8]      = v0;
    dst[l8 + 8]  = v1;
    dst[l8 + 16] = v2;
    dst[l8 + 24] = v3;
}

extern "C" void kernel_launch(void* const* d_in, const int* in_sizes, int n_in,
                              void* d_out, int out_size)
{
    const float* frame = (const float*)d_in[0];
    const float* attr  = (const float*)d_in[1];
    if (in_sizes[0] != NB * NL * 12) {
        frame = (const float*)d_in[1];
        attr  = (const float*)d_in[0];
    }

    float* eucl = (float*)d_out;                          // B*L*K*3 floats
    float* gath = (float*)d_out + (size_t)NB * NL * NK * 3;

    const int nq = NB * NL;                               // 32768 queries
    knn_kernel<<<nq / QPB, TPB>>>(frame, eucl);           // 512 blocks x 128

    const int rows = NB * NL * NK;                        // 524288
    gather_kernel<<<rows / 32, 256>>>(attr, gath);        // 4 rows/warp
}